// round 3
// baseline (speedup 1.0000x reference)
#include <cuda_runtime.h>

// VideoEmbedding: out[n,d] = sum_k basis(t_n)[k] * W[vid_n, d, k]
// N=400000, D=64, K=13, V=128.
//
// Strategy: counting-sort n by video so each warp-chunk of 32 n's shares one
// video; W[v] lives in registers (13 f32x2 per lane, lane owns d=2*lane,2*lane+1).
// Basis via one __sincosf + double-angle recurrence, splat-packed into smem,
// broadcast per n. Inner loop: 12 packed fma.rn.f32x2 per n per lane.

static constexpr int D  = 64;
static constexpr int K  = 13;   // 1 + 6 sin + 6 cos
static constexpr int MAXV = 256;
static constexpr int SORT_CAP = 1 << 20;

static constexpr int SC_BLOCK = 512;
static constexpr int SC_IPT   = 8;
static constexpr int SC_TILE  = SC_BLOCK * SC_IPT;

__device__ float g_wt[MAXV * K * D];   // transposed weights: [v][k][d]
__device__ int   g_counts[MAXV];
__device__ int   g_off[MAXV];          // padded (32-aligned) segment starts
__device__ int   g_cursor[MAXV];
__device__ int   g_sorted[SORT_CAP];   // n indices grouped by video
__device__ int   g_nchunks;

__device__ __forceinline__ unsigned long long ffma2u(unsigned long long a,
                                                     unsigned long long b,
                                                     unsigned long long c) {
    unsigned long long d;
    asm("fma.rn.f32x2 %0, %1, %2, %3;" : "=l"(d) : "l"(a), "l"(b), "l"(c));
    return d;
}
__device__ __forceinline__ unsigned long long splat2(float x) {
    unsigned long long r;
    asm("mov.b64 %0, {%1, %1};" : "=l"(r) : "f"(x));
    return r;
}

// ---------------- weight transpose [v][d][k] -> [v][k][d], + zero counts ----
__global__ void k_transpose(const float* __restrict__ w, int V) {
    if (blockIdx.x == 0 && threadIdx.x < MAXV) g_counts[threadIdx.x] = 0;
    int i = blockIdx.x * blockDim.x + threadIdx.x;
    int total = V * D * K;
    if (i < total) {
        int k = i % K;
        int d = (i / K) % D;
        int v = i / (K * D);
        g_wt[(v * K + k) * D + d] = w[i];
    }
}

// ---------------- histogram (block smem aggregation) -------------------------
__global__ void k_hist(const int* __restrict__ vids, int N) {
    __shared__ int sh[MAXV];
    for (int i = threadIdx.x; i < MAXV; i += blockDim.x) sh[i] = 0;
    __syncthreads();
    for (int i = blockIdx.x * blockDim.x + threadIdx.x; i < N;
         i += gridDim.x * blockDim.x)
        atomicAdd(&sh[vids[i]], 1);
    __syncthreads();
    for (int i = threadIdx.x; i < MAXV; i += blockDim.x) {
        int c = sh[i];
        if (c) atomicAdd(&g_counts[i], c);
    }
}

// ---------------- exclusive scan with 32-padding ----------------------------
__global__ void k_scan(int V) {
    __shared__ int sh[MAXV];
    if (threadIdx.x < V) sh[threadIdx.x] = g_counts[threadIdx.x];
    __syncthreads();
    if (threadIdx.x == 0) {
        int off = 0;
        for (int v = 0; v < V; v++) {
            g_off[v] = off;
            g_cursor[v] = off;
            off += (sh[v] + 31) & ~31;   // pad each segment to a 32 boundary
        }
        g_nchunks = off >> 5;
    }
}

// ---------------- scatter (block-aggregated ranks) --------------------------
__global__ void k_scatter(const int* __restrict__ vids, int N) {
    __shared__ int sh[MAXV];
    __shared__ int sbase[MAXV];
    for (int i = threadIdx.x; i < MAXV; i += blockDim.x) sh[i] = 0;
    __syncthreads();
    int base = blockIdx.x * SC_TILE;
    int myv[SC_IPT], myr[SC_IPT];
#pragma unroll
    for (int it = 0; it < SC_IPT; it++) {
        int i = base + it * SC_BLOCK + threadIdx.x;
        myv[it] = -1; myr[it] = 0;
        if (i < N) { myv[it] = vids[i]; myr[it] = atomicAdd(&sh[myv[it]], 1); }
    }
    __syncthreads();
    for (int i = threadIdx.x; i < MAXV; i += blockDim.x) {
        int c = sh[i];
        sbase[i] = c ? atomicAdd(&g_cursor[i], c) : 0;
    }
    __syncthreads();
#pragma unroll
    for (int it = 0; it < SC_IPT; it++) {
        int i = base + it * SC_BLOCK + threadIdx.x;
        if (i < N) g_sorted[sbase[myv[it]] + myr[it]] = i;
    }
}

// ---------------- main: per-chunk register-resident weights -----------------
__global__ void __launch_bounds__(256)
k_main(const float* __restrict__ times, const int* __restrict__ vids,
       float* __restrict__ out) {
    // per-warp basis staging: 32 lanes * 9 ulonglong2 (144B stride -> <=4-way
    // bank conflicts on the splat writes; reads are pure broadcast)
    __shared__ ulonglong2 smb[8][32 * 9];
    const int lane = threadIdx.x & 31;
    const int wib  = threadIdx.x >> 5;
    const int gw   = (blockIdx.x * blockDim.x + threadIdx.x) >> 5;
    const int nwps = (gridDim.x * blockDim.x) >> 5;
    const int NC   = g_nchunks;

    for (int c = gw; c < NC; c += nwps) {
        const int p   = c * 32 + lane;
        const int idx = g_sorted[p];         // always in [0,N): zero-init or
                                             // previously written valid index
        int v0 = 0;
        if (lane == 0) v0 = vids[idx];       // lane0 of every chunk is real
        const int v = __shfl_sync(0xffffffffu, v0, 0);
        const int seg_end = g_off[v] + g_counts[v];

        // W[v] -> registers: lane owns columns d = 2*lane, 2*lane+1
        const float* wp = g_wt + v * (K * D) + 2 * lane;
        unsigned long long w[K];
#pragma unroll
        for (int k = 0; k < K; k++)
            w[k] = *reinterpret_cast<const unsigned long long*>(wp + k * D);

        // basis for this lane's own n (garbage ok on padded lanes — skipped)
        const float t = times[idx];
        const float a = t * 3.14159265358979323846f;
        float s1, q1; __sincosf(a, &s1, &q1);
        const float s2 = 2.f * s1 * q1, q2 = fmaf(q1, q1, -s1 * s1);
        const float s3 = 2.f * s2 * q2, q3 = fmaf(q2, q2, -s2 * s2);
        const float s4 = 2.f * s3 * q3, q4 = fmaf(q3, q3, -s3 * s3);
        const float s5 = 2.f * s4 * q4, q5 = fmaf(q4, q4, -s4 * s4);
        const float s6 = 2.f * s5 * q5, q6 = fmaf(q5, q5, -s5 * s5);

        ulonglong2* bl = &smb[wib][lane * 9];
        bl[0] = make_ulonglong2(splat2(s1), splat2(s2));
        bl[1] = make_ulonglong2(splat2(s3), splat2(s4));
        bl[2] = make_ulonglong2(splat2(s5), splat2(s6));
        bl[3] = make_ulonglong2(splat2(q1), splat2(q2));
        bl[4] = make_ulonglong2(splat2(q3), splat2(q4));
        bl[5] = make_ulonglong2(splat2(q5), splat2(q6));
        __syncwarp();

        const int jmax = min(32, seg_end - c * 32);   // uniform across warp
        for (int j = 0; j < jmax; j++) {
            const int nn = __shfl_sync(0xffffffffu, idx, j);
            const ulonglong2* bj = &smb[wib][j * 9];
            const ulonglong2 B0 = bj[0], B1 = bj[1], B2 = bj[2];
            const ulonglong2 B3 = bj[3], B4 = bj[4], B5 = bj[5];
            unsigned long long acc = w[0];             // basis[0] == 1
            acc = ffma2u(B0.x, w[1],  acc);
            acc = ffma2u(B0.y, w[2],  acc);
            acc = ffma2u(B1.x, w[3],  acc);
            acc = ffma2u(B1.y, w[4],  acc);
            acc = ffma2u(B2.x, w[5],  acc);
            acc = ffma2u(B2.y, w[6],  acc);
            acc = ffma2u(B3.x, w[7],  acc);
            acc = ffma2u(B3.y, w[8],  acc);
            acc = ffma2u(B4.x, w[9],  acc);
            acc = ffma2u(B4.y, w[10], acc);
            acc = ffma2u(B5.x, w[11], acc);
            acc = ffma2u(B5.y, w[12], acc);
            *reinterpret_cast<unsigned long long*>(out + (long)nn * D + 2 * lane) = acc;
        }
        __syncwarp();
    }
}

extern "C" void kernel_launch(void* const* d_in, const int* in_sizes, int n_in,
                              void* d_out, int out_size) {
    const float* times   = (const float*)d_in[0];
    const int*   vids    = (const int*)d_in[1];
    const float* weights = (const float*)d_in[2];
    float*       out     = (float*)d_out;

    const int N = in_sizes[0];
    int V = in_sizes[2] / (D * K);
    if (V > MAXV) V = MAXV;

    const int totw = V * D * K;
    k_transpose<<<(totw + 255) / 256, 256>>>(weights, V);
    k_hist<<<132, 512>>>(vids, N);
    k_scan<<<1, 256>>>(V);
    const int sc_blocks = (N + SC_TILE - 1) / SC_TILE;
    k_scatter<<<sc_blocks, SC_BLOCK>>>(vids, N);
    const int maxchunks = N / 32 + V + 1;     // upper bound on padded chunks
    const int mblocks = (maxchunks + 7) / 8;  // 8 warps per block
    k_main<<<mblocks, 256>>>(times, vids, out);
}

// round 4
// speedup vs baseline: 1.0150x; 1.0150x over previous
#include <cuda_runtime.h>

// VideoEmbedding: out[n,d] = sum_k basis(t_n)[k] * W[vid_n, d, k]
// N=400000, D=64, K=13, V=128.
//
// 3-kernel pipeline:
//   k_prep:    weight transpose [v][d][k]->[v][k][d]  +  video histogram
//              + (last block) padded exclusive scan, chunk->video map,
//                counter reset for graph replay
//   k_scatter: counting-sort scatter of n-indices into per-video segments
//              (32-aligned), block-aggregated ranks
//   k_main:    per 32-chunk: W[v] register-resident (13 f32x2/lane),
//              basis via one __sincosf + double-angle recurrence,
//              broadcast from smem, 12 packed fma.rn.f32x2 per n per lane.

static constexpr int D  = 64;
static constexpr int K  = 13;   // 1 + 6 sin + 6 cos
static constexpr int MAXV = 256;
static constexpr int SORT_CAP = 1 << 20;

__device__ float g_wt[MAXV * K * D];      // transposed weights [v][k][d]
__device__ int   g_counts[MAXV];          // zero at load; re-zeroed every launch
__device__ int   g_off[MAXV];             // padded segment starts
__device__ int   g_end[MAXV];             // off + count (real end)
__device__ int   g_cursor[MAXV];
__device__ int   g_sorted[SORT_CAP];      // n indices grouped by video
__device__ int   g_chunkv[SORT_CAP / 32]; // chunk -> video
__device__ int   g_nchunks;
__device__ int   g_done;                  // ticket; reset by scan block

__device__ __forceinline__ unsigned long long ffma2u(unsigned long long a,
                                                     unsigned long long b,
                                                     unsigned long long c) {
    unsigned long long d;
    asm("fma.rn.f32x2 %0, %1, %2, %3;" : "=l"(d) : "l"(a), "l"(b), "l"(c));
    return d;
}
__device__ __forceinline__ unsigned long long splat2(float x) {
    unsigned long long r;
    asm("mov.b64 %0, {%1, %1};" : "=l"(r) : "f"(x));
    return r;
}

// ---------------- prep: transpose + hist + (last block) scan ----------------
__global__ void __launch_bounds__(512)
k_prep(const float* __restrict__ w, const int* __restrict__ vids,
       int N, int V, int G) {
    __shared__ int sh[MAXV];
    const int tid = threadIdx.x;
    for (int i = tid; i < MAXV; i += 512) sh[i] = 0;
    __syncthreads();

    // transpose (grid-stride)
    const int total = V * D * K;
    for (int i = blockIdx.x * 512 + tid; i < total; i += G * 512) {
        int k = i % K;
        int d = (i / K) % D;
        int v = i / (K * D);
        g_wt[(v * K + k) * D + d] = w[i];
    }

    // histogram (int4 vectorized, grid-stride)
    const int N4 = N >> 2;
    for (int i = blockIdx.x * 512 + tid; i < N4; i += G * 512) {
        int4 q = reinterpret_cast<const int4*>(vids)[i];
        atomicAdd(&sh[q.x], 1); atomicAdd(&sh[q.y], 1);
        atomicAdd(&sh[q.z], 1); atomicAdd(&sh[q.w], 1);
    }
    for (int i = (N4 << 2) + blockIdx.x * 512 + tid; i < N; i += G * 512)
        atomicAdd(&sh[vids[i]], 1);
    __syncthreads();

    for (int i = tid; i < MAXV; i += 512) {
        int c = sh[i];
        if (c) atomicAdd(&g_counts[i], c);
    }
    __threadfence();

    // ticket: last-finishing block does the scan
    __shared__ int s_last;
    if (tid == 0) s_last = (atomicAdd(&g_done, 1) == G - 1) ? 1 : 0;
    __syncthreads();
    if (!s_last) return;

    __shared__ int sc[MAXV];
    int cnt = 0, pad = 0;
    if (tid < MAXV) {
        cnt = g_counts[tid];
        pad = (cnt + 31) & ~31;          // 32-align every segment
        sc[tid] = pad;
    }
    __syncthreads();
    // inclusive Hillis-Steele over MAXV entries
    for (int s = 1; s < MAXV; s <<= 1) {
        int a = 0;
        if (tid < MAXV && tid >= s) a = sc[tid - s];
        __syncthreads();
        if (tid < MAXV) sc[tid] += a;
        __syncthreads();
    }
    if (tid < MAXV) {
        int off = sc[tid] - pad;          // exclusive
        if (tid < V) {
            g_off[tid]    = off;
            g_cursor[tid] = off;
            g_end[tid]    = off + cnt;
            for (int c = off >> 5, ce = (off + pad) >> 5; c < ce; c++)
                g_chunkv[c] = tid;
        }
        g_counts[tid] = 0;                // reset for next graph replay
    }
    if (tid == 0) {
        g_nchunks = sc[MAXV - 1] >> 5;
        g_done = 0;                       // reset ticket
    }
}

// ---------------- scatter (block-aggregated ranks, int4 loads) --------------
__global__ void __launch_bounds__(256)
k_scatter(const int* __restrict__ vids, int N) {
    __shared__ int sh[MAXV];
    __shared__ int sbase[MAXV];
    const int tid = threadIdx.x;
    sh[tid] = 0;
    if (tid + 256 < MAXV) sh[tid + 256] = 0;
    __syncthreads();

    const int base = blockIdx.x * 1024 + tid * 4;
    int v[4], r[4];
    if (base + 3 < N) {
        int4 q = *reinterpret_cast<const int4*>(vids + base);
        v[0] = q.x; v[1] = q.y; v[2] = q.z; v[3] = q.w;
#pragma unroll
        for (int j = 0; j < 4; j++) r[j] = atomicAdd(&sh[v[j]], 1);
    } else {
#pragma unroll
        for (int j = 0; j < 4; j++) {
            int i = base + j;
            v[j] = -1;
            if (i < N) { v[j] = vids[i]; r[j] = atomicAdd(&sh[v[j]], 1); }
        }
    }
    __syncthreads();
    for (int i = tid; i < MAXV; i += 256) {
        int c = sh[i];
        sbase[i] = c ? atomicAdd(&g_cursor[i], c) : 0;
    }
    __syncthreads();
#pragma unroll
    for (int j = 0; j < 4; j++)
        if (v[j] >= 0) g_sorted[sbase[v[j]] + r[j]] = base + j;
}

// ---------------- main: register-resident weights, f32x2 inner loop ---------
__global__ void __launch_bounds__(256)
k_main(const float* __restrict__ times, float* __restrict__ out) {
    __shared__ ulonglong2 smb[8][32 * 9];   // per-warp basis staging
    __shared__ int        sidx[8][32];      // per-warp n indices
    const int lane = threadIdx.x & 31;
    const int wib  = threadIdx.x >> 5;
    const int gw   = (blockIdx.x * blockDim.x + threadIdx.x) >> 5;
    const int nwps = (gridDim.x * blockDim.x) >> 5;
    const int NC   = g_nchunks;

    for (int c = gw; c < NC; c += nwps) {
        const int v   = g_chunkv[c];         // independent of g_sorted chain
        const int idx = g_sorted[c * 32 + lane];  // padding slots are 0 (valid)
        const int seg_end = g_end[v];

        // W[v] -> registers: lane owns columns d = 2*lane, 2*lane+1
        const float* wp = g_wt + v * (K * D) + 2 * lane;
        unsigned long long w[K];
#pragma unroll
        for (int k = 0; k < K; k++)
            w[k] = *reinterpret_cast<const unsigned long long*>(wp + k * D);

        // basis for this lane's n (garbage on padded lanes — never consumed)
        const float t = times[idx];
        const float a = t * 3.14159265358979323846f;
        float s1, q1; __sincosf(a, &s1, &q1);
        const float s2 = 2.f * s1 * q1, q2 = fmaf(q1, q1, -s1 * s1);
        const float s3 = 2.f * s2 * q2, q3 = fmaf(q2, q2, -s2 * s2);
        const float s4 = 2.f * s3 * q3, q4 = fmaf(q3, q3, -s3 * s3);
        const float s5 = 2.f * s4 * q4, q5 = fmaf(q4, q4, -s4 * s4);
        const float s6 = 2.f * s5 * q5, q6 = fmaf(q5, q5, -s5 * s5);

        ulonglong2* bl = &smb[wib][lane * 9];
        bl[0] = make_ulonglong2(splat2(s1), splat2(s2));
        bl[1] = make_ulonglong2(splat2(s3), splat2(s4));
        bl[2] = make_ulonglong2(splat2(s5), splat2(s6));
        bl[3] = make_ulonglong2(splat2(q1), splat2(q2));
        bl[4] = make_ulonglong2(splat2(q3), splat2(q4));
        bl[5] = make_ulonglong2(splat2(q5), splat2(q6));
        sidx[wib][lane] = idx;
        __syncwarp();

        const int jmax = min(32, seg_end - c * 32);   // warp-uniform, >= 1
        for (int j = 0; j < jmax; j++) {
            const int nn = sidx[wib][j];
            const ulonglong2* bj = &smb[wib][j * 9];
            const ulonglong2 B0 = bj[0], B1 = bj[1], B2 = bj[2];
            const ulonglong2 B3 = bj[3], B4 = bj[4], B5 = bj[5];
            unsigned long long acc = w[0];             // basis[0] == 1
            acc = ffma2u(B0.x, w[1],  acc);
            acc = ffma2u(B0.y, w[2],  acc);
            acc = ffma2u(B1.x, w[3],  acc);
            acc = ffma2u(B1.y, w[4],  acc);
            acc = ffma2u(B2.x, w[5],  acc);
            acc = ffma2u(B2.y, w[6],  acc);
            acc = ffma2u(B3.x, w[7],  acc);
            acc = ffma2u(B3.y, w[8],  acc);
            acc = ffma2u(B4.x, w[9],  acc);
            acc = ffma2u(B4.y, w[10], acc);
            acc = ffma2u(B5.x, w[11], acc);
            acc = ffma2u(B5.y, w[12], acc);
            *reinterpret_cast<unsigned long long*>(out + (long)nn * D + 2 * lane) = acc;
        }
        __syncwarp();
    }
}

extern "C" void kernel_launch(void* const* d_in, const int* in_sizes, int n_in,
                              void* d_out, int out_size) {
    const float* times   = (const float*)d_in[0];
    const int*   vids    = (const int*)d_in[1];
    const float* weights = (const float*)d_in[2];
    float*       out     = (float*)d_out;

    const int N = in_sizes[0];
    int V = in_sizes[2] / (D * K);
    if (V > MAXV) V = MAXV;

    const int totw = V * D * K;
    int G = (totw + 511) / 512;
    if (G < 160) G = 160;                 // enough threads for the histogram
    k_prep<<<G, 512>>>(weights, vids, N, V, G);

    const int sc_blocks = (N + 1023) / 1024;
    k_scatter<<<sc_blocks, 256>>>(vids, N);

    const int maxchunks = N / 32 + V + 1;
    const int mblocks = (maxchunks + 7) / 8;   // 8 warps per block
    k_main<<<mblocks, 256>>>(times, out);
}